// round 7
// baseline (speedup 1.0000x reference)
#include <cuda_runtime.h>
#include <cuda_fp16.h>

#define N_NODES 100000
#define N_EDGES 1600000
#define C_IN    64
#define C_HID   64
#define C_OUT   32

#define SCAN_BLK 512
#define N_SCAN_BLOCKS ((N_NODES + SCAN_BLK - 1) / SCAN_BLK)   // 196

#define FIXP 16777216.0f   // 2^24 fixed-point scale for ew accumulation

#define GEMM1_BLOCKS ((N_NODES + 63) / 64)        // 1563 (64 rows/block)
#define FILL_BLOCKS  ((N_EDGES / 4 + 255) / 256)  // 1563 (1024 edges/block)

// ----- scratch (device globals; no runtime allocation) ----------------------
__device__ unsigned long long g_pack[N_NODES];   // cnt<<40 | sum(ew)*2^24
__device__ float g_deg[N_NODES];                 // dinv
__device__ int   g_cnt[N_NODES];
__device__ int   g_rs [N_NODES];                 // CSR row start
__device__ int   g_rank[N_EDGES];                // edge rank within dst bucket

// decoupled-lookback scan state: (value<<2)|flag, flag: 0 none, 1 agg, 2 prefix
__device__ int                         g_tick;
__device__ volatile unsigned long long g_state[N_SCAN_BLOCKS];

struct EdgeRec { int src; float w; };            // w = ew (dinv folded into h)
__device__ EdgeRec g_csr[N_EDGES];

__device__ __align__(16) __half g_h1h[N_NODES * C_HID];  // dinv * (x @ W1)  fp16
__device__ __align__(16) float  g_o1 [N_NODES * C_HID];  // relu(layer-1 out)
__device__ __align__(16) __half g_h2h[N_NODES * C_OUT];  // dinv * (o1 @ W2) fp16

// ---------------------------------------------------------------------------
__global__ void k_init() {
    int i = blockIdx.x * blockDim.x + threadIdx.x;
    if (i < N_NODES) g_pack[i] = 0ull;
    if (i < N_SCAN_BLOCKS) g_state[i] = 0ull;
    if (i == 0) g_tick = 0;
}

// one 64-bit atomic per edge; returned old count = rank within dst bucket.
// 4 edges per thread for atomic MLP.
__global__ void k_deg(const int* __restrict__ ei, const float* __restrict__ ew) {
    int t = blockIdx.x * blockDim.x + threadIdx.x;
    if (t < N_EDGES / 4) {
        int4   d4 = ((const int4*)(ei + N_EDGES))[t];
        float4 w4 = ((const float4*)ew)[t];
        unsigned long long o0 = atomicAdd(&g_pack[d4.x],
            (1ull << 40) | (unsigned long long)(w4.x * FIXP + 0.5f));
        unsigned long long o1 = atomicAdd(&g_pack[d4.y],
            (1ull << 40) | (unsigned long long)(w4.y * FIXP + 0.5f));
        unsigned long long o2 = atomicAdd(&g_pack[d4.z],
            (1ull << 40) | (unsigned long long)(w4.z * FIXP + 0.5f));
        unsigned long long o3 = atomicAdd(&g_pack[d4.w],
            (1ull << 40) | (unsigned long long)(w4.w * FIXP + 0.5f));
        ((int4*)g_rank)[t] = make_int4((int)(o0 >> 40), (int)(o1 >> 40),
                                       (int)(o2 >> 40), (int)(o3 >> 40));
    }
}

// single-pass scan (warp-parallel decoupled lookback): cnt, dinv, g_rs
__global__ void k_scan() {
    __shared__ int warp_sums[16];
    __shared__ int sh_bid, sh_exc;
    if (threadIdx.x == 0) sh_bid = atomicAdd(&g_tick, 1);
    __syncthreads();
    int bid = sh_bid;
    int i = bid * SCAN_BLK + threadIdx.x;

    int v = 0;
    if (i < N_NODES) {
        unsigned long long p = g_pack[i];
        v = (int)(p >> 40);
        g_cnt[i] = v;
        float deg = 1.0f + (float)(p & 0xFFFFFFFFFFull) * (1.0f / FIXP);
        g_deg[i] = rsqrtf(deg);
    }

    int lane = threadIdx.x & 31, wid = threadIdx.x >> 5;
    int inc = v;
    #pragma unroll
    for (int o = 1; o < 32; o <<= 1) {
        int t = __shfl_up_sync(0xffffffffu, inc, o);
        if (lane >= o) inc += t;
    }
    if (lane == 31) warp_sums[wid] = inc;
    __syncthreads();
    if (wid == 0) {
        int s = (lane < 16) ? warp_sums[lane] : 0;
        #pragma unroll
        for (int o = 1; o < 16; o <<= 1) {
            int t = __shfl_up_sync(0xffffffffu, s, o);
            if (lane >= o) s += t;
        }
        if (lane < 16) warp_sums[lane] = s;
    }
    __syncthreads();
    int incl = inc + ((wid > 0) ? warp_sums[wid - 1] : 0);
    int total = warp_sums[15];

    if (threadIdx.x == 0)
        g_state[bid] = ((unsigned long long)total << 2) | 1ull;

    if (wid == 0) {
        int exc = 0;
        if (bid > 0) {
            int j = bid - 1;
            while (true) {
                int jj = j - lane;
                unsigned long long s;
                do {
                    s = (jj >= 0) ? g_state[jj] : 2ull;   // jj<0: prefix of 0
                } while (__any_sync(0xffffffffu, (s & 3ull) == 0ull));
                unsigned pm = __ballot_sync(0xffffffffu, (s & 3ull) == 2ull);
                if (pm) {
                    int fp = __ffs(pm) - 1;               // nearest prefix
                    int val = (lane <= fp) ? (int)(s >> 2) : 0;
                    #pragma unroll
                    for (int o = 16; o; o >>= 1)
                        val += __shfl_xor_sync(0xffffffffu, val, o);
                    exc += val;
                    break;
                } else {
                    int val = (int)(s >> 2);
                    #pragma unroll
                    for (int o = 16; o; o >>= 1)
                        val += __shfl_xor_sync(0xffffffffu, val, o);
                    exc += val;
                    j -= 32;
                }
            }
        }
        if (lane == 0) {
            g_state[bid] = ((unsigned long long)(exc + total) << 2) | 2ull;
            sh_exc = exc;
        }
    }
    __syncthreads();
    if (i < N_NODES) g_rs[i] = sh_exc + incl - v;          // exclusive
}

// ---------------------------------------------------------------------------
// MERGED: even blocks run gemm1 (FMA-bound), odd blocks run CSR fill
// (L2-latency-bound). Both depend only on k_scan; overlapping them mixes
// complementary pipes on each SM.
//
// gemm1: h1h = dinv * (x @ W1), fp16 out. Row-pair-packed smem + fma.rn.f32x2.
//   block 256 = 64 ch (tx) x 4 ty; tile 32 rows = 16 pairs; thread: 4 pairs
//   (8 rows); 2 tiles -> 64 rows/block.
// fill: slot = rs[dst] + rank[e], 4 edges/thread, no atomics.
__global__ void k_gemm1_fill(const float* __restrict__ x,
                             const float* __restrict__ W1,
                             const int*   __restrict__ ei,
                             const float* __restrict__ ew) {
    __shared__ float2 xp[64][17];           // [k][rowpair], pad -> 8.7KB

    int role = blockIdx.x & 1;
    int bid  = blockIdx.x >> 1;

    if (role == 1) {                        // ---- CSR fill ----
        int t = bid * 256 + threadIdx.x;
        if (t < N_EDGES / 4) {
            int4   s4 = ((const int4*)ei)[t];
            int4   d4 = ((const int4*)(ei + N_EDGES))[t];
            float4 w4 = ((const float4*)ew)[t];
            int4   r4 = ((const int4*)g_rank)[t];
            int rs0 = __ldg(&g_rs[d4.x]);
            int rs1 = __ldg(&g_rs[d4.y]);
            int rs2 = __ldg(&g_rs[d4.z]);
            int rs3 = __ldg(&g_rs[d4.w]);
            EdgeRec e;
            e.src = s4.x; e.w = w4.x; g_csr[rs0 + r4.x] = e;
            e.src = s4.y; e.w = w4.y; g_csr[rs1 + r4.y] = e;
            e.src = s4.z; e.w = w4.z; g_csr[rs2 + r4.z] = e;
            e.src = s4.w; e.w = w4.w; g_csr[rs3 + r4.w] = e;
        }
        return;
    }

    // ---- gemm1 ----
    int tx = threadIdx.x & 63;
    int ty = threadIdx.x >> 6;

    float wreg[64];                         // W1 column tx
    #pragma unroll
    for (int k = 0; k < 64; ++k) wreg[k] = W1[k * 64 + tx];

    int base = bid * 64;
    for (int t = 0; t < 2; ++t) {
        int row0 = base + t * 32;
        __syncthreads();
        {   // load 32 rows into row-pair layout
            int rp = threadIdx.x & 15;      // row pair 0..15
            int kc = threadIdx.x >> 4;      // k-chunk of 4 (0..15)
            int rA = row0 + 2 * rp, rB = rA + 1;
            float4 a = (rA < N_NODES)
                ? ((const float4*)(x + (size_t)rA * 64))[kc]
                : make_float4(0.f, 0.f, 0.f, 0.f);
            float4 b = (rB < N_NODES)
                ? ((const float4*)(x + (size_t)rB * 64))[kc]
                : make_float4(0.f, 0.f, 0.f, 0.f);
            xp[4 * kc + 0][rp] = make_float2(a.x, b.x);
            xp[4 * kc + 1][rp] = make_float2(a.y, b.y);
            xp[4 * kc + 2][rp] = make_float2(a.z, b.z);
            xp[4 * kc + 3][rp] = make_float2(a.w, b.w);
        }
        __syncthreads();

        unsigned long long acc0 = 0ull, acc1 = 0ull, acc2 = 0ull, acc3 = 0ull;
        #pragma unroll
        for (int k = 0; k < 64; ++k) {
            unsigned long long wp;
            asm("mov.b64 %0, {%1, %1};" : "=l"(wp) : "f"(wreg[k]));
            unsigned long long x0 = *(const unsigned long long*)&xp[k][4 * ty + 0];
            unsigned long long x1 = *(const unsigned long long*)&xp[k][4 * ty + 1];
            unsigned long long x2 = *(const unsigned long long*)&xp[k][4 * ty + 2];
            unsigned long long x3 = *(const unsigned long long*)&xp[k][4 * ty + 3];
            asm("fma.rn.f32x2 %0, %1, %2, %0;" : "+l"(acc0) : "l"(x0), "l"(wp));
            asm("fma.rn.f32x2 %0, %1, %2, %0;" : "+l"(acc1) : "l"(x1), "l"(wp));
            asm("fma.rn.f32x2 %0, %1, %2, %0;" : "+l"(acc2) : "l"(x2), "l"(wp));
            asm("fma.rn.f32x2 %0, %1, %2, %0;" : "+l"(acc3) : "l"(x3), "l"(wp));
        }

        unsigned long long accs[4] = {acc0, acc1, acc2, acc3};
        #pragma unroll
        for (int j = 0; j < 4; ++j) {
            float lo, hi;
            asm("mov.b64 {%0, %1}, %2;" : "=f"(lo), "=f"(hi) : "l"(accs[j]));
            int r = row0 + 8 * ty + 2 * j;
            if (r < N_NODES)
                g_h1h[(size_t)r * 64 + tx] = __float2half_rn(g_deg[r] * lo);
            if (r + 1 < N_NODES)
                g_h1h[(size_t)(r + 1) * 64 + tx] =
                    __float2half_rn(g_deg[r + 1] * hi);
        }
    }
}

// Aggregation layer 1: one warp per dst; unroll x8 for L2 MLP.
__global__ void k_agg1(const float* __restrict__ b1) {
    int w = (blockIdx.x * blockDim.x + threadIdx.x) >> 5;
    int lane = threadIdx.x & 31;
    if (w >= N_NODES) return;
    int beg = g_rs[w];
    int n   = g_cnt[w];
    const __half2* h1v = (const __half2*)g_h1h;

    float a0 = 0.f, a1 = 0.f;
    int i = 0;
    for (; i + 7 < n; i += 8) {
        EdgeRec e0 = g_csr[beg + i + 0];
        EdgeRec e1 = g_csr[beg + i + 1];
        EdgeRec e2 = g_csr[beg + i + 2];
        EdgeRec e3 = g_csr[beg + i + 3];
        EdgeRec e4 = g_csr[beg + i + 4];
        EdgeRec e5 = g_csr[beg + i + 5];
        EdgeRec e6 = g_csr[beg + i + 6];
        EdgeRec e7 = g_csr[beg + i + 7];
        float2 f0 = __half22float2(__ldg(h1v + (size_t)e0.src * 32 + lane));
        float2 f1 = __half22float2(__ldg(h1v + (size_t)e1.src * 32 + lane));
        float2 f2 = __half22float2(__ldg(h1v + (size_t)e2.src * 32 + lane));
        float2 f3 = __half22float2(__ldg(h1v + (size_t)e3.src * 32 + lane));
        float2 f4 = __half22float2(__ldg(h1v + (size_t)e4.src * 32 + lane));
        float2 f5 = __half22float2(__ldg(h1v + (size_t)e5.src * 32 + lane));
        float2 f6 = __half22float2(__ldg(h1v + (size_t)e6.src * 32 + lane));
        float2 f7 = __half22float2(__ldg(h1v + (size_t)e7.src * 32 + lane));
        a0 += e0.w * f0.x + e1.w * f1.x + e2.w * f2.x + e3.w * f3.x
            + e4.w * f4.x + e5.w * f5.x + e6.w * f6.x + e7.w * f7.x;
        a1 += e0.w * f0.y + e1.w * f1.y + e2.w * f2.y + e3.w * f3.y
            + e4.w * f4.y + e5.w * f5.y + e6.w * f6.y + e7.w * f7.y;
    }
    for (; i < n; ++i) {
        EdgeRec er = g_csr[beg + i];
        float2 f = __half22float2(__ldg(h1v + (size_t)er.src * 32 + lane));
        a0 += er.w * f.x;
        a1 += er.w * f.y;
    }
    float di = g_deg[w];
    float2 hs = __half22float2(h1v[(size_t)w * 32 + lane]);   // dinv-scaled
    float2 bb = ((const float2*)b1)[lane];
    a0 = di * a0 + di * hs.x + bb.x;
    a1 = di * a1 + di * hs.y + bb.y;
    ((float2*)g_o1)[(size_t)w * 32 + lane] =
        make_float2(fmaxf(a0, 0.f), fmaxf(a1, 0.f));
}

// GEMM2: h2h = dinv * (o1 @ W2), fp16 out. Row-pair packed + fma.rn.f32x2.
// block 256 = 32 ch (tx) x 8 ty; tile 32 rows = 16 pairs; thread: 2 pairs;
// 4 tiles -> 128 rows/block.
__global__ void k_gemm2(const float* __restrict__ W2) {
    __shared__ float2 xp[64][17];

    int tx = threadIdx.x & 31;
    int ty = threadIdx.x >> 5;

    float wreg[64];
    #pragma unroll
    for (int k = 0; k < 64; ++k) wreg[k] = W2[k * 32 + tx];

    int base = blockIdx.x * 128;
    for (int t = 0; t < 4; ++t) {
        int row0 = base + t * 32;
        __syncthreads();
        {
            int rp = threadIdx.x & 15;
            int kc = threadIdx.x >> 4;
            int rA = row0 + 2 * rp, rB = rA + 1;
            float4 a = (rA < N_NODES)
                ? ((const float4*)(g_o1 + (size_t)rA * 64))[kc]
                : make_float4(0.f, 0.f, 0.f, 0.f);
            float4 b = (rB < N_NODES)
                ? ((const float4*)(g_o1 + (size_t)rB * 64))[kc]
                : make_float4(0.f, 0.f, 0.f, 0.f);
            xp[4 * kc + 0][rp] = make_float2(a.x, b.x);
            xp[4 * kc + 1][rp] = make_float2(a.y, b.y);
            xp[4 * kc + 2][rp] = make_float2(a.z, b.z);
            xp[4 * kc + 3][rp] = make_float2(a.w, b.w);
        }
        __syncthreads();

        unsigned long long acc0 = 0ull, acc1 = 0ull;
        #pragma unroll
        for (int k = 0; k < 64; ++k) {
            unsigned long long wp;
            asm("mov.b64 %0, {%1, %1};" : "=l"(wp) : "f"(wreg[k]));
            unsigned long long x0 = *(const unsigned long long*)&xp[k][2 * ty + 0];
            unsigned long long x1 = *(const unsigned long long*)&xp[k][2 * ty + 1];
            asm("fma.rn.f32x2 %0, %1, %2, %0;" : "+l"(acc0) : "l"(x0), "l"(wp));
            asm("fma.rn.f32x2 %0, %1, %2, %0;" : "+l"(acc1) : "l"(x1), "l"(wp));
        }

        unsigned long long accs[2] = {acc0, acc1};
        #pragma unroll
        for (int j = 0; j < 2; ++j) {
            float lo, hi;
            asm("mov.b64 {%0, %1}, %2;" : "=f"(lo), "=f"(hi) : "l"(accs[j]));
            int r = row0 + 4 * ty + 2 * j;
            if (r < N_NODES)
                g_h2h[(size_t)r * 32 + tx] = __float2half_rn(g_deg[r] * lo);
            if (r + 1 < N_NODES)
                g_h2h[(size_t)(r + 1) * 32 + tx] =
                    __float2half_rn(g_deg[r + 1] * hi);
        }
    }
}

// Aggregation layer 2: warp per dst; half-warps interleave edges, unroll x4.
__global__ void k_agg2(const float* __restrict__ b2, float* __restrict__ out) {
    int w = (blockIdx.x * blockDim.x + threadIdx.x) >> 5;
    int lane = threadIdx.x & 31;
    if (w >= N_NODES) return;
    int half = lane >> 4;
    int c2   = lane & 15;
    int beg = g_rs[w];
    int n   = g_cnt[w];
    const __half2* h2v = (const __half2*)g_h2h;

    float a0 = 0.f, a1 = 0.f;
    int i = half;
    for (; i + 6 < n; i += 8) {
        EdgeRec ea = g_csr[beg + i];
        EdgeRec eb = g_csr[beg + i + 2];
        EdgeRec ec = g_csr[beg + i + 4];
        EdgeRec ed = g_csr[beg + i + 6];
        float2 fa = __half22float2(__ldg(h2v + (size_t)ea.src * 16 + c2));
        float2 fb = __half22float2(__ldg(h2v + (size_t)eb.src * 16 + c2));
        float2 fc = __half22float2(__ldg(h2v + (size_t)ec.src * 16 + c2));
        float2 fd = __half22float2(__ldg(h2v + (size_t)ed.src * 16 + c2));
        a0 += ea.w * fa.x + eb.w * fb.x + ec.w * fc.x + ed.w * fd.x;
        a1 += ea.w * fa.y + eb.w * fb.y + ec.w * fc.y + ed.w * fd.y;
    }
    for (; i < n; i += 2) {
        EdgeRec er = g_csr[beg + i];
        float2 f = __half22float2(__ldg(h2v + (size_t)er.src * 16 + c2));
        a0 += er.w * f.x;
        a1 += er.w * f.y;
    }
    a0 += __shfl_xor_sync(0xffffffffu, a0, 16);
    a1 += __shfl_xor_sync(0xffffffffu, a1, 16);

    if (half == 0) {
        float di = g_deg[w];
        float2 hs = __half22float2(h2v[(size_t)w * 16 + c2]);   // dinv-scaled
        float2 bb = ((const float2*)b2)[c2];
        float o0  = di * a0 + di * hs.x + bb.x;
        float o1v = di * a1 + di * hs.y + bb.y;
        ((float2*)out)[(size_t)w * 16 + c2] = make_float2(o0, o1v);
    }
}

// ---------------------------------------------------------------------------
extern "C" void kernel_launch(void* const* d_in, const int* in_sizes, int n_in,
                              void* d_out, int out_size) {
    const float* x  = (const float*)d_in[0];
    const int*   ei = (const int*)d_in[1];
    const float* ew = (const float*)d_in[2];
    const float* W1 = (const float*)d_in[3];
    const float* b1 = (const float*)d_in[4];
    const float* W2 = (const float*)d_in[5];
    const float* b2 = (const float*)d_in[6];
    float* out = (float*)d_out;

    k_init <<<(N_NODES + 255) / 256, 256>>>();
    k_deg  <<<(N_EDGES / 4 + 255) / 256, 256>>>(ei, ew);
    k_scan <<<N_SCAN_BLOCKS, SCAN_BLK>>>();

    k_gemm1_fill<<<GEMM1_BLOCKS + FILL_BLOCKS, 256>>>(x, W1, ei, ew);

    k_agg1 <<<(N_NODES * 32 + 255) / 256, 256>>>(b1);
    k_gemm2<<<(N_NODES + 127) / 128, 256>>>(W2);
    k_agg2 <<<(N_NODES * 32 + 255) / 256, 256>>>(b2, out);
}